// round 13
// baseline (speedup 1.0000x reference)
#include <cuda_runtime.h>
#include <cstdint>

#define BATCH 256

__device__ float g_bufA[BATCH * 64 * 32 * 32]; // 64 MB
__device__ float g_bufB[BATCH * 64 * 32 * 32];

// ---- packed f32x2 helpers --------------------------------------------------
typedef unsigned long long f2_t;

__device__ __forceinline__ f2_t pk2(float a, float b) {
    f2_t r;
    asm("mov.b64 %0, {%1, %2};" : "=l"(r)
        : "r"(__float_as_uint(a)), "r"(__float_as_uint(b)));
    return r;
}
__device__ __forceinline__ void upk2(f2_t v, float& a, float& b) {
    unsigned lo, hi;
    asm("mov.b64 {%0, %1}, %2;" : "=r"(lo), "=r"(hi) : "l"(v));
    a = __uint_as_float(lo);
    b = __uint_as_float(hi);
}
__device__ __forceinline__ f2_t fma2(f2_t a, f2_t b, f2_t c) {
    f2_t d;
    asm("fma.rn.f32x2 %0, %1, %2, %3;" : "=l"(d) : "l"(a), "l"(b), "l"(c));
    return d;
}

// ---------------------------------------------------------------------------
// Layer 0
// ---------------------------------------------------------------------------
__global__ __launch_bounds__(256)
void k_layer0(const float* __restrict__ x, const float* __restrict__ W0,
              const float* __restrict__ b0, float* __restrict__ out)
{
    __shared__ float ws[512];
    __shared__ float bs[64];
    const int tid = threadIdx.x;
    for (int t = tid; t < 512; t += 256) {
        int oc = t >> 3, r = t & 7;
        ws[t] = W0[oc * 16 + r];
    }
    if (tid < 64) bs[tid] = b0[tid];
    __syncthreads();

    const int pos = blockIdx.x * 256 + tid;
    const int b = blockIdx.y;
    const int i = pos >> 5, j = pos & 31;
    const int pr1 = (2 * i + 1 == 63) ? 0 : 2 * i + 1;
    const int pc1 = (2 * j + 1 == 63) ? 0 : 2 * j + 1;
    int R[4]  = {2 * i, 2 * i + 1, pr1, pr1 + 1};
    int Cc[4] = {2 * j, 2 * j + 1, pc1, pc1 + 1};

    const float* xb = x + (size_t)b * 4096;
    float rp[16], rn[16];
#pragma unroll
    for (int a = 0; a < 4; a++)
#pragma unroll
        for (int c = 0; c < 4; c++) {
            float v = xb[R[a] * 64 + Cc[c]];
            rp[a * 4 + c] = fmaxf(v, 0.f);
            rn[a * 4 + c] = fmaxf(-v, 0.f);
        }

    float* ob = out + (size_t)b * 64 * 1024 + i * 32 + j;
#pragma unroll 8
    for (int oc = 0; oc < 64; oc++) {
        const float* w = &ws[oc * 8];
        const float bias = bs[oc];
        float acc = 0.f;
#pragma unroll
        for (int P = 0; P < 2; P++)
#pragma unroll
            for (int Q = 0; Q < 2; Q++) {
                float s = bias;
#pragma unroll
                for (int kh = 0; kh < 2; kh++)
#pragma unroll
                    for (int kw = 0; kw < 2; kw++) {
                        int idx = (2 * P + kh) * 4 + (2 * Q + kw);
                        s = fmaf(rp[idx], w[kh * 2 + kw], s);
                        s = fmaf(rn[idx], w[4 + kh * 2 + kw], s);
                    }
                acc += fmaxf(s, 0.f);
            }
        ob[oc * 1024] = 0.25f * acc;
    }
}

// ---------------------------------------------------------------------------
// Recursion level S>=4 (R7-proven): 8 oc/thread, parity-plane smem,
// conv-grid wrap via rt/ct select tables, MINB=3 -> 24 warps/SM.
// ---------------------------------------------------------------------------
template <int S, int BB, int G, int MINB>
__global__ __launch_bounds__(256, MINB)
void k_layer(const float* __restrict__ in, const float* __restrict__ W,
             const float* __restrict__ bias, float* __restrict__ out)
{
    constexpr int H = S / 2;
    constexpr int HH = H * H;
    constexpr int Nin = G * G;
    constexpr int Nout = 4 * Nin;
    constexpr int CB = S * S;
    constexpr int CHB = 16 * CB;
    constexpr int WCS = 1024;
    constexpr int perB = 16 * S * S;
    constexpr int ITERS = (BB * HH) / 32;

    extern __shared__ float sm[];
    float* ws  = sm;              // 4*WCS : ws[child][tap(ci*4+kh*2+kw)][16oc]
    float* bs  = sm + 4 * WCS;
    float* ins = bs + 64;

    const int tid = threadIdx.x;
    const int n = blockIdx.x;
    const int b0 = blockIdx.y * BB;

    const float* Wg = W + (size_t)n * 4096;
    for (int t = tid; t < 4096; t += 256) {
        int ol = t >> 6, tap = t & 63;
        ws[(ol >> 4) * WCS + tap * 16 + (ol & 15)] = Wg[t];
    }
    if (tid < 64) bs[tid] = bias[n * 64 + tid];

    for (int t = tid; t < BB * perB; t += 256) {
        int bl = t / perB, rem = t - bl * perB;
        int ci = rem / CB, sp = rem - ci * CB;
        int r = sp / S, c = sp - r * S;
        ins[bl * CHB + ci * CB + ((r & 1) * 2 + (c & 1)) * HH
            + (r >> 1) * H + (c >> 1)]
            = in[((size_t)(b0 + bl) * Nin + n) * perB + rem];
    }
    __syncthreads();

    const int Ay = n / G, Ax = n % G;
    const int lane = tid & 31, warp = tid >> 5;
    const int child = warp & 3;
    const int half = warp >> 2;

    const float* wc = ws + child * WCS + half * 8;
    const int yl = child >> 1, xl = child & 1;
    const int nprime = (2 * Ay + yl) * (2 * G) + (2 * Ax + xl);

#pragma unroll 1
    for (int it = 0; it < ITERS; it++) {
        const int v = lane + (it << 5);
        const int j = v % H;
        const int i = (v / H) % H;
        const int bl = v / HH;

        const bool wi = (i == H - 1);
        const bool wj = (j == H - 1);
        const int rt1 = 2 * HH + i * H;
        const int rt[4] = {i * H, rt1, wi ? 0 : rt1, wi ? 2 * HH : (i + 1) * H};
        const int ct1 = HH + j;
        const int ct[4] = {j, ct1, wj ? 0 : ct1, wj ? HH : (j + 1)};

        const float* ib = ins + bl * CHB;

        f2_t acc[4][4]; // [oc-pair m][pool tap]
#pragma unroll
        for (int m = 0; m < 4; m++) {
            f2_t bv = pk2(bs[child * 16 + half * 8 + 2 * m],
                          bs[child * 16 + half * 8 + 2 * m + 1]);
            acc[m][0] = bv; acc[m][1] = bv; acc[m][2] = bv; acc[m][3] = bv;
        }

#pragma unroll 2
        for (int ci = 0; ci < 16; ci++) {
            const float* cb = ib + ci * CB;
#pragma unroll
            for (int kh = 0; kh < 2; kh++)
#pragma unroll
                for (int kw = 0; kw < 2; kw++) {
                    float x0 = cb[rt[kh]     + ct[kw]];
                    float x1 = cb[rt[kh]     + ct[2 + kw]];
                    float x2 = cb[rt[2 + kh] + ct[kw]];
                    float x3 = cb[rt[2 + kh] + ct[2 + kw]];
                    const ulonglong2* wt2 =
                        (const ulonglong2*)(wc + (ci * 4 + kh * 2 + kw) * 16);
                    ulonglong2 wA = wt2[0];
                    ulonglong2 wB = wt2[1];
                    f2_t vs0 = pk2(x0, x0), vs1 = pk2(x1, x1);
                    f2_t vs2 = pk2(x2, x2), vs3 = pk2(x3, x3);
                    acc[0][0] = fma2(wA.x, vs0, acc[0][0]);
                    acc[0][1] = fma2(wA.x, vs1, acc[0][1]);
                    acc[0][2] = fma2(wA.x, vs2, acc[0][2]);
                    acc[0][3] = fma2(wA.x, vs3, acc[0][3]);
                    acc[1][0] = fma2(wA.y, vs0, acc[1][0]);
                    acc[1][1] = fma2(wA.y, vs1, acc[1][1]);
                    acc[1][2] = fma2(wA.y, vs2, acc[1][2]);
                    acc[1][3] = fma2(wA.y, vs3, acc[1][3]);
                    acc[2][0] = fma2(wB.x, vs0, acc[2][0]);
                    acc[2][1] = fma2(wB.x, vs1, acc[2][1]);
                    acc[2][2] = fma2(wB.x, vs2, acc[2][2]);
                    acc[2][3] = fma2(wB.x, vs3, acc[2][3]);
                    acc[3][0] = fma2(wB.y, vs0, acc[3][0]);
                    acc[3][1] = fma2(wB.y, vs1, acc[3][1]);
                    acc[3][2] = fma2(wB.y, vs2, acc[3][2]);
                    acc[3][3] = fma2(wB.y, vs3, acc[3][3]);
                }
        }

        float* ob = out + ((size_t)(b0 + bl) * Nout + nprime) * 16 * HH
                        + (half * 8) * HH + i * H + j;
#pragma unroll
        for (int m = 0; m < 4; m++) {
            float a0, c0, a1, c1, a2, c2, a3, c3;
            upk2(acc[m][0], a0, c0);
            upk2(acc[m][1], a1, c1);
            upk2(acc[m][2], a2, c2);
            upk2(acc[m][3], a3, c3);
            float e = fmaxf(a0, 0.f) + fmaxf(a1, 0.f) + fmaxf(a2, 0.f) + fmaxf(a3, 0.f);
            float o = fmaxf(c0, 0.f) + fmaxf(c1, 0.f) + fmaxf(c2, 0.f) + fmaxf(c3, 0.f);
            ob[(2 * m) * HH]     = 0.25f * e;
            ob[(2 * m + 1) * HH] = 0.25f * o;
        }
    }
}

// ---------------------------------------------------------------------------
// Layer 5 special (S=2): s=1 => all 4 pool taps are the SAME conv cell, so
// out = relu(bias + conv(0,0)) and the work is 4x smaller. Thread = (child,
// 2 batch slots) x 16 oc: acc = 16 f2; per ci 8 scalar input LDS (distinct
// banks, CHB=65 ≡ 1 mod 32) + 16 weight LDS.128 broadcasts per 64 fma2.
// ---------------------------------------------------------------------------
__global__ __launch_bounds__(256, 4)
void k_layer5(const float* __restrict__ in, const float* __restrict__ W,
              const float* __restrict__ bias, float* __restrict__ out)
{
    constexpr int G = 32, Nin = 1024, Nout = 4096, BB = 128;
    constexpr int CHB = 65;      // 64 data + 1 pad (bank rotation across bl)
    constexpr int WCS = 1024;

    extern __shared__ float sm[];
    float* ws  = sm;             // 4*WCS
    float* bs  = sm + 4 * WCS;   // 64
    float* ins = bs + 64;        // BB*CHB

    const int tid = threadIdx.x;
    const int n = blockIdx.x;
    const int b0 = blockIdx.y * BB;

    const float* Wg = W + (size_t)n * 4096;
    for (int t = tid; t < 4096; t += 256) {
        int ol = t >> 6, tap = t & 63;
        ws[(ol >> 4) * WCS + tap * 16 + (ol & 15)] = Wg[t];
    }
    if (tid < 64) bs[tid] = bias[n * 64 + tid];

    // stage: rem = ci*4 + kh*2 + kw already matches tap order
    for (int t = tid; t < BB * 64; t += 256) {
        int bl = t >> 6, rem = t & 63;
        ins[bl * CHB + rem] = in[((size_t)(b0 + bl) * Nin + n) * 64 + rem];
    }
    __syncthreads();

    const int Ay = n / G, Ax = n % G;
    const int lane = tid & 31, warp = tid >> 5;
    const int child = warp & 3;
    const int blg = warp >> 2;            // 0/1
    const float* wc = ws + child * WCS;
    const int yl = child >> 1, xl = child & 1;
    const int nprime = (2 * Ay + yl) * (2 * G) + (2 * Ax + xl);

    const int bl0 = blg * 64 + lane;      // this thread's two batch slots
    const int bl1 = bl0 + 32;
    const float* ibA = ins + bl0 * CHB;
    const float* ibB = ins + bl1 * CHB;

    f2_t acc[8][2]; // [oc-pair][batch slot]
#pragma unroll
    for (int k = 0; k < 8; k++) {
        f2_t bv = pk2(bs[child * 16 + 2 * k], bs[child * 16 + 2 * k + 1]);
        acc[k][0] = bv; acc[k][1] = bv;
    }

#pragma unroll 4
    for (int ci = 0; ci < 16; ci++) {
#pragma unroll
        for (int t = 0; t < 4; t++) {
            float xa = ibA[ci * 4 + t];
            float xb = ibB[ci * 4 + t];
            f2_t vsA = pk2(xa, xa), vsB = pk2(xb, xb);
            const ulonglong2* wt2 = (const ulonglong2*)(wc + (ci * 4 + t) * 16);
            ulonglong2 w01 = wt2[0];   // oc pairs 0,1
            ulonglong2 w23 = wt2[1];   // oc pairs 2,3
            ulonglong2 w45 = wt2[2];   // oc pairs 4,5
            ulonglong2 w67 = wt2[3];   // oc pairs 6,7
            acc[0][0] = fma2(w01.x, vsA, acc[0][0]);
            acc[0][1] = fma2(w01.x, vsB, acc[0][1]);
            acc[1][0] = fma2(w01.y, vsA, acc[1][0]);
            acc[1][1] = fma2(w01.y, vsB, acc[1][1]);
            acc[2][0] = fma2(w23.x, vsA, acc[2][0]);
            acc[2][1] = fma2(w23.x, vsB, acc[2][1]);
            acc[3][0] = fma2(w23.y, vsA, acc[3][0]);
            acc[3][1] = fma2(w23.y, vsB, acc[3][1]);
            acc[4][0] = fma2(w45.x, vsA, acc[4][0]);
            acc[4][1] = fma2(w45.x, vsB, acc[4][1]);
            acc[5][0] = fma2(w45.y, vsA, acc[5][0]);
            acc[5][1] = fma2(w45.y, vsB, acc[5][1]);
            acc[6][0] = fma2(w67.x, vsA, acc[6][0]);
            acc[6][1] = fma2(w67.x, vsB, acc[6][1]);
            acc[7][0] = fma2(w67.y, vsA, acc[7][0]);
            acc[7][1] = fma2(w67.y, vsB, acc[7][1]);
        }
    }

#pragma unroll
    for (int s = 0; s < 2; s++) {
        int bl = s ? bl1 : bl0;
        float* ob = out + ((size_t)(b0 + bl) * Nout + nprime) * 16;
#pragma unroll
        for (int q = 0; q < 4; q++) {
            float a0, a1, a2, a3;
            upk2(acc[2 * q][s], a0, a1);
            upk2(acc[2 * q + 1][s], a2, a3);
            float4 o;
            o.x = fmaxf(a0, 0.f); o.y = fmaxf(a1, 0.f);
            o.z = fmaxf(a2, 0.f); o.w = fmaxf(a3, 0.f);
            *(float4*)(ob + 4 * q) = o;
        }
    }
}

// ---------------------------------------------------------------------------
// FT layer
// ---------------------------------------------------------------------------
__global__ __launch_bounds__(256)
void k_ft(const float* __restrict__ v, const float* __restrict__ Wft,
          const float* __restrict__ bft, float* __restrict__ out)
{
    const int n = blockIdx.x * 256 + threadIdx.x;
    const int b = blockIdx.y;
    const float* vp = v + ((size_t)b * 4096 + n) * 16;
    float vv[16];
#pragma unroll
    for (int c = 0; c < 16; c += 4) {
        float4 t = *(const float4*)(vp + c);
        vv[c] = t.x; vv[c + 1] = t.y; vv[c + 2] = t.z; vv[c + 3] = t.w;
    }
    const float* wp = Wft + (size_t)n * 64;
    float f[4];
#pragma unroll
    for (int o = 0; o < 4; o++) {
        float acc = bft[n * 4 + o];
#pragma unroll
        for (int c = 0; c < 16; c++) acc = fmaf(vv[c], wp[o * 16 + c], acc);
        f[o] = acc;
    }
    out[(size_t)b * 8192 + n]        = f[0] - f[1];
    out[(size_t)b * 8192 + 4096 + n] = f[2] - f[3];
}

// ---------------------------------------------------------------------------

template <int S, int BB>
static inline int smem_b() {
    return (4 * 1024 + 64 + BB * 16 * S * S) * 4;
}

extern "C" void kernel_launch(void* const* d_in, const int* in_sizes, int n_in,
                              void* d_out, int out_size)
{
    (void)n_in; (void)out_size;
    const float* x  = (const float*)d_in[0];
    const float* W0 = (const float*)d_in[1];
    const float* b0 = (const float*)d_in[2];
    const float *W1, *b1, *W2, *b2, *W3, *b3, *W4, *b4, *W5, *b5, *Wft, *bft;
    if (in_sizes[3] == 262144) {
        Wft = (const float*)d_in[3];  bft = (const float*)d_in[4];
        W1 = (const float*)d_in[5];   b1 = (const float*)d_in[6];
        W2 = (const float*)d_in[7];   b2 = (const float*)d_in[8];
        W3 = (const float*)d_in[9];   b3 = (const float*)d_in[10];
        W4 = (const float*)d_in[11];  b4 = (const float*)d_in[12];
        W5 = (const float*)d_in[13];  b5 = (const float*)d_in[14];
    } else {
        W1 = (const float*)d_in[3];   b1 = (const float*)d_in[4];
        W2 = (const float*)d_in[5];   b2 = (const float*)d_in[6];
        W3 = (const float*)d_in[7];   b3 = (const float*)d_in[8];
        W4 = (const float*)d_in[9];   b4 = (const float*)d_in[10];
        W5 = (const float*)d_in[11];  b5 = (const float*)d_in[12];
        Wft = (const float*)d_in[13]; bft = (const float*)d_in[14];
    }
    float* out = (float*)d_out;

    float *bufA, *bufB;
    cudaGetSymbolAddress((void**)&bufA, g_bufA);
    cudaGetSymbolAddress((void**)&bufB, g_bufB);

    const int s1 = smem_b<32, 1>();
    const int s2 = smem_b<16, 1>();
    const int s3 = smem_b<8, 4>();
    const int s4 = smem_b<4, 16>();
    const int s5 = (4 * 1024 + 64 + 128 * 65) * 4;
    cudaFuncSetAttribute(k_layer<32, 1, 2, 2>,   cudaFuncAttributeMaxDynamicSharedMemorySize, s1);
    cudaFuncSetAttribute(k_layer<16, 1, 4, 3>,   cudaFuncAttributeMaxDynamicSharedMemorySize, s2);
    cudaFuncSetAttribute(k_layer<8, 4, 8, 3>,    cudaFuncAttributeMaxDynamicSharedMemorySize, s3);
    cudaFuncSetAttribute(k_layer<4, 16, 16, 3>,  cudaFuncAttributeMaxDynamicSharedMemorySize, s4);
    cudaFuncSetAttribute(k_layer5,               cudaFuncAttributeMaxDynamicSharedMemorySize, s5);

    k_layer0<<<dim3(4, BATCH), 256>>>(x, W0, b0, bufA);
    k_layer<32, 1, 2, 2><<<dim3(4, 256), 256, s1>>>(bufA, W1, b1, bufB);
    k_layer<16, 1, 4, 3><<<dim3(16, 256), 256, s2>>>(bufB, W2, b2, bufA);
    k_layer<8, 4, 8, 3><<<dim3(64, 64), 256, s3>>>(bufA, W3, b3, bufB);
    k_layer<4, 16, 16, 3><<<dim3(256, 16), 256, s4>>>(bufB, W4, b4, bufA);
    k_layer5<<<dim3(1024, 2), 256, s5>>>(bufA, W5, b5, bufB);
    k_ft<<<dim3(16, BATCH), 256>>>(bufB, Wft, bft, out);
}

// round 14
// speedup vs baseline: 1.5617x; 1.5617x over previous
#include <cuda_runtime.h>
#include <cstdint>

#define BATCH 256

__device__ float g_bufA[BATCH * 64 * 32 * 32]; // 64 MB
__device__ float g_bufB[BATCH * 64 * 32 * 32];

// ---- packed f32x2 helpers --------------------------------------------------
typedef unsigned long long f2_t;

__device__ __forceinline__ f2_t pk2(float a, float b) {
    f2_t r;
    asm("mov.b64 %0, {%1, %2};" : "=l"(r)
        : "r"(__float_as_uint(a)), "r"(__float_as_uint(b)));
    return r;
}
__device__ __forceinline__ void upk2(f2_t v, float& a, float& b) {
    unsigned lo, hi;
    asm("mov.b64 {%0, %1}, %2;" : "=r"(lo), "=r"(hi) : "l"(v));
    a = __uint_as_float(lo);
    b = __uint_as_float(hi);
}
__device__ __forceinline__ f2_t fma2(f2_t a, f2_t b, f2_t c) {
    f2_t d;
    asm("fma.rn.f32x2 %0, %1, %2, %3;" : "=l"(d) : "l"(a), "l"(b), "l"(c));
    return d;
}

// ---------------------------------------------------------------------------
// Layer 0
// ---------------------------------------------------------------------------
__global__ __launch_bounds__(256)
void k_layer0(const float* __restrict__ x, const float* __restrict__ W0,
              const float* __restrict__ b0, float* __restrict__ out)
{
    __shared__ float ws[512];
    __shared__ float bs[64];
    const int tid = threadIdx.x;
    for (int t = tid; t < 512; t += 256) {
        int oc = t >> 3, r = t & 7;
        ws[t] = W0[oc * 16 + r];
    }
    if (tid < 64) bs[tid] = b0[tid];
    __syncthreads();

    const int pos = blockIdx.x * 256 + tid;
    const int b = blockIdx.y;
    const int i = pos >> 5, j = pos & 31;
    const int pr1 = (2 * i + 1 == 63) ? 0 : 2 * i + 1;
    const int pc1 = (2 * j + 1 == 63) ? 0 : 2 * j + 1;
    int R[4]  = {2 * i, 2 * i + 1, pr1, pr1 + 1};
    int Cc[4] = {2 * j, 2 * j + 1, pc1, pc1 + 1};

    const float* xb = x + (size_t)b * 4096;
    float rp[16], rn[16];
#pragma unroll
    for (int a = 0; a < 4; a++)
#pragma unroll
        for (int c = 0; c < 4; c++) {
            float v = xb[R[a] * 64 + Cc[c]];
            rp[a * 4 + c] = fmaxf(v, 0.f);
            rn[a * 4 + c] = fmaxf(-v, 0.f);
        }

    float* ob = out + (size_t)b * 64 * 1024 + i * 32 + j;
#pragma unroll 8
    for (int oc = 0; oc < 64; oc++) {
        const float* w = &ws[oc * 8];
        const float bias = bs[oc];
        float acc = 0.f;
#pragma unroll
        for (int P = 0; P < 2; P++)
#pragma unroll
            for (int Q = 0; Q < 2; Q++) {
                float s = bias;
#pragma unroll
                for (int kh = 0; kh < 2; kh++)
#pragma unroll
                    for (int kw = 0; kw < 2; kw++) {
                        int idx = (2 * P + kh) * 4 + (2 * Q + kw);
                        s = fmaf(rp[idx], w[kh * 2 + kw], s);
                        s = fmaf(rn[idx], w[4 + kh * 2 + kw], s);
                    }
                acc += fmaxf(s, 0.f);
            }
        ob[oc * 1024] = 0.25f * acc;
    }
}

// ---------------------------------------------------------------------------
// Recursion level (R3-proven, 1237us config): 16 oc/thread, parity-plane smem,
// conv-grid wrap via rt/ct select tables, child-uniform warps, MINB=2.
// Only change vs R3: larger BB to amortize per-CTA weight staging.
// ---------------------------------------------------------------------------
template <int S, int BB, int G>
__global__ __launch_bounds__(256, 2)
void k_layer(const float* __restrict__ in, const float* __restrict__ W,
             const float* __restrict__ bias, float* __restrict__ out)
{
    constexpr int H = S / 2;
    constexpr int HH = H * H;
    constexpr int Nin = G * G;
    constexpr int Nout = 4 * Nin;
    constexpr int CB = S * S;
    constexpr int PAD = (HH < 32) ? HH : 0;
    constexpr int CHB = 16 * CB + PAD;
    constexpr int WCS = 1024;
    constexpr int perB = 16 * S * S;
    constexpr int ITERS = (BB * HH) / 64;

    extern __shared__ float sm[];
    float* ws  = sm;              // 4*WCS : ws[child][tap(ci*4+kh*2+kw)][16oc]
    float* bs  = sm + 4 * WCS;
    float* ins = bs + 64;

    const int tid = threadIdx.x;
    const int n = blockIdx.x;
    const int b0 = blockIdx.y * BB;

    const float* Wg = W + (size_t)n * 4096;
    for (int t = tid; t < 4096; t += 256) {
        int ol = t >> 6, tap = t & 63;
        ws[(ol >> 4) * WCS + tap * 16 + (ol & 15)] = Wg[t];
    }
    if (tid < 64) bs[tid] = bias[n * 64 + tid];

    for (int t = tid; t < BB * perB; t += 256) {
        int bl = t / perB, rem = t - bl * perB;
        int ci = rem / CB, sp = rem - ci * CB;
        int r = sp / S, c = sp - r * S;
        ins[bl * CHB + ci * CB + ((r & 1) * 2 + (c & 1)) * HH
            + (r >> 1) * H + (c >> 1)]
            = in[((size_t)(b0 + bl) * Nin + n) * perB + rem];
    }
    __syncthreads();

    const int Ay = n / G, Ax = n % G;
    const int lane = tid & 31, warp = tid >> 5;
    const int child = warp & 3;
    const int wk0 = lane + ((warp >> 2) << 5);   // 0..63

    const float* wc = ws + child * WCS;
    const int yl = child >> 1, xl = child & 1;
    const int nprime = (2 * Ay + yl) * (2 * G) + (2 * Ax + xl);

#pragma unroll
    for (int it = 0; it < ITERS; it++) {
        const int v = wk0 + (it << 6);
        const int j = v % H;
        const int i = (v / H) % H;
        const int bl = v / HH;

        const bool wi = (i == H - 1);
        const bool wj = (j == H - 1);
        const int rt1 = 2 * HH + i * H;
        const int rt[4] = {i * H, rt1, wi ? 0 : rt1, wi ? 2 * HH : (i + 1) * H};
        const int ct1 = HH + j;
        const int ct[4] = {j, ct1, wj ? 0 : ct1, wj ? HH : (j + 1)};

        const float* ib = ins + bl * CHB;

        f2_t acc[8][4];
#pragma unroll
        for (int k = 0; k < 8; k++) {
            f2_t bv = pk2(bs[child * 16 + 2 * k], bs[child * 16 + 2 * k + 1]);
            acc[k][0] = bv; acc[k][1] = bv; acc[k][2] = bv; acc[k][3] = bv;
        }

#pragma unroll 4
        for (int ci = 0; ci < 16; ci++) {
            const float* cb = ib + ci * CB;
            float xv[4][4];
#pragma unroll
            for (int a = 0; a < 4; a++)
#pragma unroll
                for (int b = 0; b < 4; b++)
                    xv[a][b] = cb[rt[a] + ct[b]];

#pragma unroll
            for (int kh = 0; kh < 2; kh++)
#pragma unroll
                for (int kw = 0; kw < 2; kw++) {
                    const ulonglong2* wt2 =
                        (const ulonglong2*)(wc + (ci * 4 + kh * 2 + kw) * 16);
                    f2_t vs0 = pk2(xv[kh][kw],         xv[kh][kw]);
                    f2_t vs1 = pk2(xv[kh][2 + kw],     xv[kh][2 + kw]);
                    f2_t vs2 = pk2(xv[2 + kh][kw],     xv[2 + kh][kw]);
                    f2_t vs3 = pk2(xv[2 + kh][2 + kw], xv[2 + kh][2 + kw]);
#pragma unroll
                    for (int m = 0; m < 4; m++) {
                        ulonglong2 ww = wt2[m];
                        acc[2 * m][0]     = fma2(ww.x, vs0, acc[2 * m][0]);
                        acc[2 * m][1]     = fma2(ww.x, vs1, acc[2 * m][1]);
                        acc[2 * m][2]     = fma2(ww.x, vs2, acc[2 * m][2]);
                        acc[2 * m][3]     = fma2(ww.x, vs3, acc[2 * m][3]);
                        acc[2 * m + 1][0] = fma2(ww.y, vs0, acc[2 * m + 1][0]);
                        acc[2 * m + 1][1] = fma2(ww.y, vs1, acc[2 * m + 1][1]);
                        acc[2 * m + 1][2] = fma2(ww.y, vs2, acc[2 * m + 1][2]);
                        acc[2 * m + 1][3] = fma2(ww.y, vs3, acc[2 * m + 1][3]);
                    }
                }
        }

        float* ob = out + ((size_t)(b0 + bl) * Nout + nprime) * 16 * HH
                        + i * H + j;
#pragma unroll
        for (int k = 0; k < 8; k++) {
            float a0, c0, a1, c1, a2, c2, a3, c3;
            upk2(acc[k][0], a0, c0);
            upk2(acc[k][1], a1, c1);
            upk2(acc[k][2], a2, c2);
            upk2(acc[k][3], a3, c3);
            float e = fmaxf(a0, 0.f) + fmaxf(a1, 0.f) + fmaxf(a2, 0.f) + fmaxf(a3, 0.f);
            float o = fmaxf(c0, 0.f) + fmaxf(c1, 0.f) + fmaxf(c2, 0.f) + fmaxf(c3, 0.f);
            ob[(2 * k) * HH]     = 0.25f * e;
            ob[(2 * k + 1) * HH] = 0.25f * o;
        }
    }
}

// ---------------------------------------------------------------------------
// FT layer with smem-cached Wft: grid (16 n-blocks, 16 batch-blocks); each CTA
// stages its 256-n Wft slice (+bias) once and reuses it for 16 batches.
// Wft gmem traffic: 268 MB -> 17 MB.
// ---------------------------------------------------------------------------
__global__ __launch_bounds__(256)
void k_ft(const float* __restrict__ v, const float* __restrict__ Wft,
          const float* __restrict__ bft, float* __restrict__ out)
{
    constexpr int WROW = 65;  // padded per-n weight row (64 + 1, bank rotate)
    extern __shared__ float sm[];
    float* ws = sm;            // 256 * WROW
    float* bs = sm + 256 * WROW; // 1024

    const int tid = threadIdx.x;
    const int nb = blockIdx.x;       // n-block: n = nb*256 + tid
    const int yb = blockIdx.y;       // batch block of 16

    for (int t = tid; t < 256 * 64; t += 256) {
        int r = t >> 6, c = t & 63;
        ws[r * WROW + c] = Wft[(size_t)nb * 16384 + t];
    }
    for (int t = tid; t < 1024; t += 256)
        bs[t] = bft[nb * 1024 + t];
    __syncthreads();

    const int n = nb * 256 + tid;
    const float* wp = ws + tid * WROW;

#pragma unroll 1
    for (int bb = 0; bb < 16; bb++) {
        const int b = yb * 16 + bb;
        const float* vp = v + ((size_t)b * 4096 + n) * 16;
        float vv[16];
#pragma unroll
        for (int c = 0; c < 16; c += 4) {
            float4 t = *(const float4*)(vp + c);
            vv[c] = t.x; vv[c + 1] = t.y; vv[c + 2] = t.z; vv[c + 3] = t.w;
        }
        float f[4];
#pragma unroll
        for (int o = 0; o < 4; o++) {
            float acc = bs[tid * 4 + o];
#pragma unroll
            for (int c = 0; c < 16; c++) acc = fmaf(vv[c], wp[o * 16 + c], acc);
            f[o] = acc;
        }
        out[(size_t)b * 8192 + n]        = f[0] - f[1];
        out[(size_t)b * 8192 + 4096 + n] = f[2] - f[3];
    }
}

// ---------------------------------------------------------------------------

template <int S, int BB>
static inline int smem_b() {
    int HH = (S / 2) * (S / 2);
    int pad = (HH < 32) ? HH : 0;
    return (4 * 1024 + 64 + BB * (16 * S * S + pad)) * 4;
}

extern "C" void kernel_launch(void* const* d_in, const int* in_sizes, int n_in,
                              void* d_out, int out_size)
{
    (void)n_in; (void)out_size;
    const float* x  = (const float*)d_in[0];
    const float* W0 = (const float*)d_in[1];
    const float* b0 = (const float*)d_in[2];
    const float *W1, *b1, *W2, *b2, *W3, *b3, *W4, *b4, *W5, *b5, *Wft, *bft;
    if (in_sizes[3] == 262144) {
        Wft = (const float*)d_in[3];  bft = (const float*)d_in[4];
        W1 = (const float*)d_in[5];   b1 = (const float*)d_in[6];
        W2 = (const float*)d_in[7];   b2 = (const float*)d_in[8];
        W3 = (const float*)d_in[9];   b3 = (const float*)d_in[10];
        W4 = (const float*)d_in[11];  b4 = (const float*)d_in[12];
        W5 = (const float*)d_in[13];  b5 = (const float*)d_in[14];
    } else {
        W1 = (const float*)d_in[3];   b1 = (const float*)d_in[4];
        W2 = (const float*)d_in[5];   b2 = (const float*)d_in[6];
        W3 = (const float*)d_in[7];   b3 = (const float*)d_in[8];
        W4 = (const float*)d_in[9];   b4 = (const float*)d_in[10];
        W5 = (const float*)d_in[11];  b5 = (const float*)d_in[12];
        Wft = (const float*)d_in[13]; bft = (const float*)d_in[14];
    }
    float* out = (float*)d_out;

    float *bufA, *bufB;
    cudaGetSymbolAddress((void**)&bufA, g_bufA);
    cudaGetSymbolAddress((void**)&bufB, g_bufB);

    // BB maximized within the 114 KB / 2-CTA smem budget (ITERS=4 everywhere):
    const int s1 = smem_b<32, 1>();    // ~82 KB
    const int s2 = smem_b<16, 4>();    // ~82 KB
    const int s3 = smem_b<8, 16>();    // ~83 KB
    const int s4 = smem_b<4, 64>();    // ~83 KB
    const int s5 = smem_b<2, 256>();   // ~83 KB
    const int sft = (256 * 65 + 1024) * 4;  // ~70 KB
    cudaFuncSetAttribute(k_layer<32, 1, 2>,    cudaFuncAttributeMaxDynamicSharedMemorySize, s1);
    cudaFuncSetAttribute(k_layer<16, 4, 4>,    cudaFuncAttributeMaxDynamicSharedMemorySize, s2);
    cudaFuncSetAttribute(k_layer<8, 16, 8>,    cudaFuncAttributeMaxDynamicSharedMemorySize, s3);
    cudaFuncSetAttribute(k_layer<4, 64, 16>,   cudaFuncAttributeMaxDynamicSharedMemorySize, s4);
    cudaFuncSetAttribute(k_layer<2, 256, 32>,  cudaFuncAttributeMaxDynamicSharedMemorySize, s5);
    cudaFuncSetAttribute(k_ft,                 cudaFuncAttributeMaxDynamicSharedMemorySize, sft);

    k_layer0<<<dim3(4, BATCH), 256>>>(x, W0, b0, bufA);
    k_layer<32, 1, 2><<<dim3(4, 256), 256, s1>>>(bufA, W1, b1, bufB);
    k_layer<16, 4, 4><<<dim3(16, 64), 256, s2>>>(bufB, W2, b2, bufA);
    k_layer<8, 16, 8><<<dim3(64, 16), 256, s3>>>(bufA, W3, b3, bufB);
    k_layer<4, 64, 16><<<dim3(256, 4), 256, s4>>>(bufB, W4, b4, bufA);
    k_layer<2, 256, 32><<<dim3(1024, 1), 256, s5>>>(bufA, W5, b5, bufB);
    k_ft<<<dim3(16, 16), 256, sft>>>(bufB, Wft, bft, out);
}

// round 15
// speedup vs baseline: 1.7386x; 1.1133x over previous
#include <cuda_runtime.h>
#include <cstdint>

#define BATCH 256

__device__ float g_bufA[BATCH * 64 * 32 * 32]; // 64 MB
__device__ float g_bufB[BATCH * 64 * 32 * 32];

// ---- packed f32x2 helpers --------------------------------------------------
typedef unsigned long long f2_t;

__device__ __forceinline__ f2_t pk2(float a, float b) {
    f2_t r;
    asm("mov.b64 %0, {%1, %2};" : "=l"(r)
        : "r"(__float_as_uint(a)), "r"(__float_as_uint(b)));
    return r;
}
__device__ __forceinline__ void upk2(f2_t v, float& a, float& b) {
    unsigned lo, hi;
    asm("mov.b64 {%0, %1}, %2;" : "=r"(lo), "=r"(hi) : "l"(v));
    a = __uint_as_float(lo);
    b = __uint_as_float(hi);
}
__device__ __forceinline__ f2_t fma2(f2_t a, f2_t b, f2_t c) {
    f2_t d;
    asm("fma.rn.f32x2 %0, %1, %2, %3;" : "=l"(d) : "l"(a), "l"(b), "l"(c));
    return d;
}

// ---------------------------------------------------------------------------
// Layer 0
// ---------------------------------------------------------------------------
__global__ __launch_bounds__(256)
void k_layer0(const float* __restrict__ x, const float* __restrict__ W0,
              const float* __restrict__ b0, float* __restrict__ out)
{
    __shared__ float ws[512];
    __shared__ float bs[64];
    const int tid = threadIdx.x;
    for (int t = tid; t < 512; t += 256) {
        int oc = t >> 3, r = t & 7;
        ws[t] = W0[oc * 16 + r];
    }
    if (tid < 64) bs[tid] = b0[tid];
    __syncthreads();

    const int pos = blockIdx.x * 256 + tid;
    const int b = blockIdx.y;
    const int i = pos >> 5, j = pos & 31;
    const int pr1 = (2 * i + 1 == 63) ? 0 : 2 * i + 1;
    const int pc1 = (2 * j + 1 == 63) ? 0 : 2 * j + 1;
    int R[4]  = {2 * i, 2 * i + 1, pr1, pr1 + 1};
    int Cc[4] = {2 * j, 2 * j + 1, pc1, pc1 + 1};

    const float* xb = x + (size_t)b * 4096;
    float rp[16], rn[16];
#pragma unroll
    for (int a = 0; a < 4; a++)
#pragma unroll
        for (int c = 0; c < 4; c++) {
            float v = xb[R[a] * 64 + Cc[c]];
            rp[a * 4 + c] = fmaxf(v, 0.f);
            rn[a * 4 + c] = fmaxf(-v, 0.f);
        }

    float* ob = out + (size_t)b * 64 * 1024 + i * 32 + j;
#pragma unroll 8
    for (int oc = 0; oc < 64; oc++) {
        const float* w = &ws[oc * 8];
        const float bias = bs[oc];
        float acc = 0.f;
#pragma unroll
        for (int P = 0; P < 2; P++)
#pragma unroll
            for (int Q = 0; Q < 2; Q++) {
                float s = bias;
#pragma unroll
                for (int kh = 0; kh < 2; kh++)
#pragma unroll
                    for (int kw = 0; kw < 2; kw++) {
                        int idx = (2 * P + kh) * 4 + (2 * Q + kw);
                        s = fmaf(rp[idx], w[kh * 2 + kw], s);
                        s = fmaf(rn[idx], w[4 + kh * 2 + kw], s);
                    }
                acc += fmaxf(s, 0.f);
            }
        ob[oc * 1024] = 0.25f * acc;
    }
}

// ---------------------------------------------------------------------------
// Recursion level (R14-proven): 16 oc/thread, parity-plane smem, conv-grid
// wrap via rt/ct select tables, child-uniform warps, MINB=2, large BB.
// ---------------------------------------------------------------------------
template <int S, int BB, int G>
__global__ __launch_bounds__(256, 2)
void k_layer(const float* __restrict__ in, const float* __restrict__ W,
             const float* __restrict__ bias, float* __restrict__ out)
{
    constexpr int H = S / 2;
    constexpr int HH = H * H;
    constexpr int Nin = G * G;
    constexpr int Nout = 4 * Nin;
    constexpr int CB = S * S;
    constexpr int PAD = (HH < 32) ? HH : 0;
    constexpr int CHB = 16 * CB + PAD;
    constexpr int WCS = 1024;
    constexpr int perB = 16 * S * S;
    constexpr int ITERS = (BB * HH) / 64;

    extern __shared__ float sm[];
    float* ws  = sm;              // 4*WCS : ws[child][tap(ci*4+kh*2+kw)][16oc]
    float* bs  = sm + 4 * WCS;
    float* ins = bs + 64;

    const int tid = threadIdx.x;
    const int n = blockIdx.x;
    const int b0 = blockIdx.y * BB;

    const float* Wg = W + (size_t)n * 4096;
    for (int t = tid; t < 4096; t += 256) {
        int ol = t >> 6, tap = t & 63;
        ws[(ol >> 4) * WCS + tap * 16 + (ol & 15)] = Wg[t];
    }
    if (tid < 64) bs[tid] = bias[n * 64 + tid];

    for (int t = tid; t < BB * perB; t += 256) {
        int bl = t / perB, rem = t - bl * perB;
        int ci = rem / CB, sp = rem - ci * CB;
        int r = sp / S, c = sp - r * S;
        ins[bl * CHB + ci * CB + ((r & 1) * 2 + (c & 1)) * HH
            + (r >> 1) * H + (c >> 1)]
            = in[((size_t)(b0 + bl) * Nin + n) * perB + rem];
    }
    __syncthreads();

    const int Ay = n / G, Ax = n % G;
    const int lane = tid & 31, warp = tid >> 5;
    const int child = warp & 3;
    const int wk0 = lane + ((warp >> 2) << 5);   // 0..63

    const float* wc = ws + child * WCS;
    const int yl = child >> 1, xl = child & 1;
    const int nprime = (2 * Ay + yl) * (2 * G) + (2 * Ax + xl);

#pragma unroll
    for (int it = 0; it < ITERS; it++) {
        const int v = wk0 + (it << 6);
        const int j = v % H;
        const int i = (v / H) % H;
        const int bl = v / HH;

        const bool wi = (i == H - 1);
        const bool wj = (j == H - 1);
        const int rt1 = 2 * HH + i * H;
        const int rt[4] = {i * H, rt1, wi ? 0 : rt1, wi ? 2 * HH : (i + 1) * H};
        const int ct1 = HH + j;
        const int ct[4] = {j, ct1, wj ? 0 : ct1, wj ? HH : (j + 1)};

        const float* ib = ins + bl * CHB;

        f2_t acc[8][4];
#pragma unroll
        for (int k = 0; k < 8; k++) {
            f2_t bv = pk2(bs[child * 16 + 2 * k], bs[child * 16 + 2 * k + 1]);
            acc[k][0] = bv; acc[k][1] = bv; acc[k][2] = bv; acc[k][3] = bv;
        }

#pragma unroll 4
        for (int ci = 0; ci < 16; ci++) {
            const float* cb = ib + ci * CB;
            float xv[4][4];
#pragma unroll
            for (int a = 0; a < 4; a++)
#pragma unroll
                for (int b = 0; b < 4; b++)
                    xv[a][b] = cb[rt[a] + ct[b]];

#pragma unroll
            for (int kh = 0; kh < 2; kh++)
#pragma unroll
                for (int kw = 0; kw < 2; kw++) {
                    const ulonglong2* wt2 =
                        (const ulonglong2*)(wc + (ci * 4 + kh * 2 + kw) * 16);
                    f2_t vs0 = pk2(xv[kh][kw],         xv[kh][kw]);
                    f2_t vs1 = pk2(xv[kh][2 + kw],     xv[kh][2 + kw]);
                    f2_t vs2 = pk2(xv[2 + kh][kw],     xv[2 + kh][kw]);
                    f2_t vs3 = pk2(xv[2 + kh][2 + kw], xv[2 + kh][2 + kw]);
#pragma unroll
                    for (int m = 0; m < 4; m++) {
                        ulonglong2 ww = wt2[m];
                        acc[2 * m][0]     = fma2(ww.x, vs0, acc[2 * m][0]);
                        acc[2 * m][1]     = fma2(ww.x, vs1, acc[2 * m][1]);
                        acc[2 * m][2]     = fma2(ww.x, vs2, acc[2 * m][2]);
                        acc[2 * m][3]     = fma2(ww.x, vs3, acc[2 * m][3]);
                        acc[2 * m + 1][0] = fma2(ww.y, vs0, acc[2 * m + 1][0]);
                        acc[2 * m + 1][1] = fma2(ww.y, vs1, acc[2 * m + 1][1]);
                        acc[2 * m + 1][2] = fma2(ww.y, vs2, acc[2 * m + 1][2]);
                        acc[2 * m + 1][3] = fma2(ww.y, vs3, acc[2 * m + 1][3]);
                    }
                }
        }

        float* ob = out + ((size_t)(b0 + bl) * Nout + nprime) * 16 * HH
                        + i * H + j;
#pragma unroll
        for (int k = 0; k < 8; k++) {
            float a0, c0, a1, c1, a2, c2, a3, c3;
            upk2(acc[k][0], a0, c0);
            upk2(acc[k][1], a1, c1);
            upk2(acc[k][2], a2, c2);
            upk2(acc[k][3], a3, c3);
            float e = fmaxf(a0, 0.f) + fmaxf(a1, 0.f) + fmaxf(a2, 0.f) + fmaxf(a3, 0.f);
            float o = fmaxf(c0, 0.f) + fmaxf(c1, 0.f) + fmaxf(c2, 0.f) + fmaxf(c3, 0.f);
            ob[(2 * k) * HH]     = 0.25f * e;
            ob[(2 * k + 1) * HH] = 0.25f * o;
        }
    }
}

// ---------------------------------------------------------------------------
// Layer 5 special (S=2): conv grid is 1x1 and wrap-pad makes all 4 pool taps
// the SAME cell => out = relu(bias + conv). Same inner-loop shape as generic
// (16 LDS.128 + 16 scalar LDS + 16 pk2 + 128 fma2 per ci) but the 4 acc
// columns are 4 BATCH SLOTS -> 1/4 total FMAs. Input lane stride = 65 words
// (== 1 mod 32) -> conflict-free. MINB=2, no reg cap risk.
// ---------------------------------------------------------------------------
__global__ __launch_bounds__(256, 2)
void k_layer5(const float* __restrict__ in, const float* __restrict__ W,
              const float* __restrict__ bias, float* __restrict__ out)
{
    constexpr int G = 32, Nin = 1024, Nout = 4096, BB = 256;
    constexpr int CHB = 65;      // 64 data + 1 pad (lane stride 65 ≡ 1 mod 32)
    constexpr int WCS = 1024;

    extern __shared__ float sm[];
    float* ws  = sm;             // 4*WCS
    float* bs  = sm + 4 * WCS;   // 64
    float* ins = bs + 64;        // BB*CHB

    const int tid = threadIdx.x;
    const int n = blockIdx.x;

    const float* Wg = W + (size_t)n * 4096;
    for (int t = tid; t < 4096; t += 256) {
        int ol = t >> 6, tap = t & 63;
        ws[(ol >> 4) * WCS + tap * 16 + (ol & 15)] = Wg[t];
    }
    if (tid < 64) bs[tid] = bias[n * 64 + tid];

    // rem = ci*4 + kh*2 + kw already matches tap order for S=2
    for (int t = tid; t < BB * 64; t += 256) {
        int bl = t >> 6, rem = t & 63;
        ins[bl * CHB + rem] = in[((size_t)bl * Nin + n) * 64 + rem];
    }
    __syncthreads();

    const int Ay = n / G, Ax = n % G;
    const int lane = tid & 31, warp = tid >> 5;
    const int child = warp & 3;
    const int wk0 = lane + ((warp >> 2) << 5);   // 0..63

    const float* wc = ws + child * WCS;
    const int yl = child >> 1, xl = child & 1;
    const int nprime = (2 * Ay + yl) * (2 * G) + (2 * Ax + xl);

    // this thread's 4 batch slots: wk0, wk0+64, wk0+128, wk0+192
    const float* ib = ins + wk0 * CHB;

    f2_t acc[8][4]; // [oc-pair][batch slot]
#pragma unroll
    for (int k = 0; k < 8; k++) {
        f2_t bv = pk2(bs[child * 16 + 2 * k], bs[child * 16 + 2 * k + 1]);
        acc[k][0] = bv; acc[k][1] = bv; acc[k][2] = bv; acc[k][3] = bv;
    }

#pragma unroll 4
    for (int ci = 0; ci < 16; ci++) {
#pragma unroll
        for (int t = 0; t < 4; t++) {
            float x0 = ib[ci * 4 + t];
            float x1 = ib[64 * CHB + ci * 4 + t];
            float x2 = ib[128 * CHB + ci * 4 + t];
            float x3 = ib[192 * CHB + ci * 4 + t];
            const ulonglong2* wt2 = (const ulonglong2*)(wc + (ci * 4 + t) * 16);
            f2_t vs0 = pk2(x0, x0), vs1 = pk2(x1, x1);
            f2_t vs2 = pk2(x2, x2), vs3 = pk2(x3, x3);
#pragma unroll
            for (int m = 0; m < 4; m++) {
                ulonglong2 ww = wt2[m];
                acc[2 * m][0]     = fma2(ww.x, vs0, acc[2 * m][0]);
                acc[2 * m][1]     = fma2(ww.x, vs1, acc[2 * m][1]);
                acc[2 * m][2]     = fma2(ww.x, vs2, acc[2 * m][2]);
                acc[2 * m][3]     = fma2(ww.x, vs3, acc[2 * m][3]);
                acc[2 * m + 1][0] = fma2(ww.y, vs0, acc[2 * m + 1][0]);
                acc[2 * m + 1][1] = fma2(ww.y, vs1, acc[2 * m + 1][1]);
                acc[2 * m + 1][2] = fma2(ww.y, vs2, acc[2 * m + 1][2]);
                acc[2 * m + 1][3] = fma2(ww.y, vs3, acc[2 * m + 1][3]);
            }
        }
    }

#pragma unroll
    for (int s = 0; s < 4; s++) {
        const int bl = wk0 + 64 * s;
        float* ob = out + ((size_t)bl * Nout + nprime) * 16;
#pragma unroll
        for (int q = 0; q < 4; q++) {
            float a0, a1, a2, a3;
            upk2(acc[2 * q][s], a0, a1);
            upk2(acc[2 * q + 1][s], a2, a3);
            float4 o;
            o.x = fmaxf(a0, 0.f); o.y = fmaxf(a1, 0.f);
            o.z = fmaxf(a2, 0.f); o.w = fmaxf(a3, 0.f);
            *(float4*)(ob + 4 * q) = o;
        }
    }
}

// ---------------------------------------------------------------------------
// FT layer with smem-cached Wft (R14-proven).
// ---------------------------------------------------------------------------
__global__ __launch_bounds__(256)
void k_ft(const float* __restrict__ v, const float* __restrict__ Wft,
          const float* __restrict__ bft, float* __restrict__ out)
{
    constexpr int WROW = 65;
    extern __shared__ float sm[];
    float* ws = sm;              // 256 * WROW
    float* bs = sm + 256 * WROW; // 1024

    const int tid = threadIdx.x;
    const int nb = blockIdx.x;
    const int yb = blockIdx.y;

    for (int t = tid; t < 256 * 64; t += 256) {
        int r = t >> 6, c = t & 63;
        ws[r * WROW + c] = Wft[(size_t)nb * 16384 + t];
    }
    for (int t = tid; t < 1024; t += 256)
        bs[t] = bft[nb * 1024 + t];
    __syncthreads();

    const int n = nb * 256 + tid;
    const float* wp = ws + tid * WROW;

#pragma unroll 1
    for (int bb = 0; bb < 16; bb++) {
        const int b = yb * 16 + bb;
        const float* vp = v + ((size_t)b * 4096 + n) * 16;
        float vv[16];
#pragma unroll
        for (int c = 0; c < 16; c += 4) {
            float4 t = *(const float4*)(vp + c);
            vv[c] = t.x; vv[c + 1] = t.y; vv[c + 2] = t.z; vv[c + 3] = t.w;
        }
        float f[4];
#pragma unroll
        for (int o = 0; o < 4; o++) {
            float acc = bs[tid * 4 + o];
#pragma unroll
            for (int c = 0; c < 16; c++) acc = fmaf(vv[c], wp[o * 16 + c], acc);
            f[o] = acc;
        }
        out[(size_t)b * 8192 + n]        = f[0] - f[1];
        out[(size_t)b * 8192 + 4096 + n] = f[2] - f[3];
    }
}

// ---------------------------------------------------------------------------

template <int S, int BB>
static inline int smem_b() {
    int HH = (S / 2) * (S / 2);
    int pad = (HH < 32) ? HH : 0;
    return (4 * 1024 + 64 + BB * (16 * S * S + pad)) * 4;
}

extern "C" void kernel_launch(void* const* d_in, const int* in_sizes, int n_in,
                              void* d_out, int out_size)
{
    (void)n_in; (void)out_size;
    const float* x  = (const float*)d_in[0];
    const float* W0 = (const float*)d_in[1];
    const float* b0 = (const float*)d_in[2];
    const float *W1, *b1, *W2, *b2, *W3, *b3, *W4, *b4, *W5, *b5, *Wft, *bft;
    if (in_sizes[3] == 262144) {
        Wft = (const float*)d_in[3];  bft = (const float*)d_in[4];
        W1 = (const float*)d_in[5];   b1 = (const float*)d_in[6];
        W2 = (const float*)d_in[7];   b2 = (const float*)d_in[8];
        W3 = (const float*)d_in[9];   b3 = (const float*)d_in[10];
        W4 = (const float*)d_in[11];  b4 = (const float*)d_in[12];
        W5 = (const float*)d_in[13];  b5 = (const float*)d_in[14];
    } else {
        W1 = (const float*)d_in[3];   b1 = (const float*)d_in[4];
        W2 = (const float*)d_in[5];   b2 = (const float*)d_in[6];
        W3 = (const float*)d_in[7];   b3 = (const float*)d_in[8];
        W4 = (const float*)d_in[9];   b4 = (const float*)d_in[10];
        W5 = (const float*)d_in[11];  b5 = (const float*)d_in[12];
        Wft = (const float*)d_in[13]; bft = (const float*)d_in[14];
    }
    float* out = (float*)d_out;

    float *bufA, *bufB;
    cudaGetSymbolAddress((void**)&bufA, g_bufA);
    cudaGetSymbolAddress((void**)&bufB, g_bufB);

    const int s1 = smem_b<32, 1>();    // ~82 KB
    const int s2 = smem_b<16, 4>();    // ~82 KB
    const int s3 = smem_b<8, 16>();    // ~83 KB
    const int s4 = smem_b<4, 64>();    // ~83 KB
    const int s5 = (4 * 1024 + 64 + 256 * 65) * 4;  // ~83 KB
    const int sft = (256 * 65 + 1024) * 4;          // ~70 KB
    cudaFuncSetAttribute(k_layer<32, 1, 2>,    cudaFuncAttributeMaxDynamicSharedMemorySize, s1);
    cudaFuncSetAttribute(k_layer<16, 4, 4>,    cudaFuncAttributeMaxDynamicSharedMemorySize, s2);
    cudaFuncSetAttribute(k_layer<8, 16, 8>,    cudaFuncAttributeMaxDynamicSharedMemorySize, s3);
    cudaFuncSetAttribute(k_layer<4, 64, 16>,   cudaFuncAttributeMaxDynamicSharedMemorySize, s4);
    cudaFuncSetAttribute(k_layer5,             cudaFuncAttributeMaxDynamicSharedMemorySize, s5);
    cudaFuncSetAttribute(k_ft,                 cudaFuncAttributeMaxDynamicSharedMemorySize, sft);

    k_layer0<<<dim3(4, BATCH), 256>>>(x, W0, b0, bufA);
    k_layer<32, 1, 2><<<dim3(4, 256), 256, s1>>>(bufA, W1, b1, bufB);
    k_layer<16, 4, 4><<<dim3(16, 64), 256, s2>>>(bufB, W2, b2, bufA);
    k_layer<8, 16, 8><<<dim3(64, 16), 256, s3>>>(bufA, W3, b3, bufB);
    k_layer<4, 64, 16><<<dim3(256, 4), 256, s4>>>(bufB, W4, b4, bufA);
    k_layer5<<<dim3(1024, 1), 256, s5>>>(bufA, W5, b5, bufB);
    k_ft<<<dim3(16, 16), 256, sft>>>(bufB, Wft, bft, out);
}

// round 16
// speedup vs baseline: 1.8321x; 1.0538x over previous
#include <cuda_runtime.h>
#include <cstdint>

#define BATCH 256

__device__ float g_bufA[BATCH * 64 * 32 * 32]; // 64 MB
__device__ float g_bufB[BATCH * 64 * 32 * 32];

// ---- packed f32x2 helpers --------------------------------------------------
typedef unsigned long long f2_t;

__device__ __forceinline__ f2_t pk2(float a, float b) {
    f2_t r;
    asm("mov.b64 %0, {%1, %2};" : "=l"(r)
        : "r"(__float_as_uint(a)), "r"(__float_as_uint(b)));
    return r;
}
__device__ __forceinline__ void upk2(f2_t v, float& a, float& b) {
    unsigned lo, hi;
    asm("mov.b64 {%0, %1}, %2;" : "=r"(lo), "=r"(hi) : "l"(v));
    a = __uint_as_float(lo);
    b = __uint_as_float(hi);
}
__device__ __forceinline__ f2_t fma2(f2_t a, f2_t b, f2_t c) {
    f2_t d;
    asm("fma.rn.f32x2 %0, %1, %2, %3;" : "=l"(d) : "l"(a), "l"(b), "l"(c));
    return d;
}

// ---------------------------------------------------------------------------
// Layer 0
// ---------------------------------------------------------------------------
__global__ __launch_bounds__(256)
void k_layer0(const float* __restrict__ x, const float* __restrict__ W0,
              const float* __restrict__ b0, float* __restrict__ out)
{
    __shared__ float ws[512];
    __shared__ float bs[64];
    const int tid = threadIdx.x;
    for (int t = tid; t < 512; t += 256) {
        int oc = t >> 3, r = t & 7;
        ws[t] = W0[oc * 16 + r];
    }
    if (tid < 64) bs[tid] = b0[tid];
    __syncthreads();

    const int pos = blockIdx.x * 256 + tid;
    const int b = blockIdx.y;
    const int i = pos >> 5, j = pos & 31;
    const int pr1 = (2 * i + 1 == 63) ? 0 : 2 * i + 1;
    const int pc1 = (2 * j + 1 == 63) ? 0 : 2 * j + 1;
    int R[4]  = {2 * i, 2 * i + 1, pr1, pr1 + 1};
    int Cc[4] = {2 * j, 2 * j + 1, pc1, pc1 + 1};

    const float* xb = x + (size_t)b * 4096;
    float rp[16], rn[16];
#pragma unroll
    for (int a = 0; a < 4; a++)
#pragma unroll
        for (int c = 0; c < 4; c++) {
            float v = xb[R[a] * 64 + Cc[c]];
            rp[a * 4 + c] = fmaxf(v, 0.f);
            rn[a * 4 + c] = fmaxf(-v, 0.f);
        }

    float* ob = out + (size_t)b * 64 * 1024 + i * 32 + j;
#pragma unroll 8
    for (int oc = 0; oc < 64; oc++) {
        const float* w = &ws[oc * 8];
        const float bias = bs[oc];
        float acc = 0.f;
#pragma unroll
        for (int P = 0; P < 2; P++)
#pragma unroll
            for (int Q = 0; Q < 2; Q++) {
                float s = bias;
#pragma unroll
                for (int kh = 0; kh < 2; kh++)
#pragma unroll
                    for (int kw = 0; kw < 2; kw++) {
                        int idx = (2 * P + kh) * 4 + (2 * Q + kw);
                        s = fmaf(rp[idx], w[kh * 2 + kw], s);
                        s = fmaf(rn[idx], w[4 + kh * 2 + kw], s);
                    }
                acc += fmaxf(s, 0.f);
            }
        ob[oc * 1024] = 0.25f * acc;
    }
}

// ---------------------------------------------------------------------------
// Recursion level (R14-proven): 16 oc/thread, parity-plane smem, conv-grid
// wrap via rt/ct select tables, child-uniform warps, MINB=2, large BB.
// Used for L1..L3.
// ---------------------------------------------------------------------------
template <int S, int BB, int G>
__global__ __launch_bounds__(256, 2)
void k_layer(const float* __restrict__ in, const float* __restrict__ W,
             const float* __restrict__ bias, float* __restrict__ out)
{
    constexpr int H = S / 2;
    constexpr int HH = H * H;
    constexpr int Nin = G * G;
    constexpr int Nout = 4 * Nin;
    constexpr int CB = S * S;
    constexpr int PAD = (HH < 32) ? HH : 0;
    constexpr int CHB = 16 * CB + PAD;
    constexpr int WCS = 1024;
    constexpr int perB = 16 * S * S;
    constexpr int ITERS = (BB * HH) / 64;

    extern __shared__ float sm[];
    float* ws  = sm;              // 4*WCS : ws[child][tap(ci*4+kh*2+kw)][16oc]
    float* bs  = sm + 4 * WCS;
    float* ins = bs + 64;

    const int tid = threadIdx.x;
    const int n = blockIdx.x;
    const int b0 = blockIdx.y * BB;

    const float* Wg = W + (size_t)n * 4096;
    for (int t = tid; t < 4096; t += 256) {
        int ol = t >> 6, tap = t & 63;
        ws[(ol >> 4) * WCS + tap * 16 + (ol & 15)] = Wg[t];
    }
    if (tid < 64) bs[tid] = bias[n * 64 + tid];

    for (int t = tid; t < BB * perB; t += 256) {
        int bl = t / perB, rem = t - bl * perB;
        int ci = rem / CB, sp = rem - ci * CB;
        int r = sp / S, c = sp - r * S;
        ins[bl * CHB + ci * CB + ((r & 1) * 2 + (c & 1)) * HH
            + (r >> 1) * H + (c >> 1)]
            = in[((size_t)(b0 + bl) * Nin + n) * perB + rem];
    }
    __syncthreads();

    const int Ay = n / G, Ax = n % G;
    const int lane = tid & 31, warp = tid >> 5;
    const int child = warp & 3;
    const int wk0 = lane + ((warp >> 2) << 5);   // 0..63

    const float* wc = ws + child * WCS;
    const int yl = child >> 1, xl = child & 1;
    const int nprime = (2 * Ay + yl) * (2 * G) + (2 * Ax + xl);

#pragma unroll
    for (int it = 0; it < ITERS; it++) {
        const int v = wk0 + (it << 6);
        const int j = v % H;
        const int i = (v / H) % H;
        const int bl = v / HH;

        const bool wi = (i == H - 1);
        const bool wj = (j == H - 1);
        const int rt1 = 2 * HH + i * H;
        const int rt[4] = {i * H, rt1, wi ? 0 : rt1, wi ? 2 * HH : (i + 1) * H};
        const int ct1 = HH + j;
        const int ct[4] = {j, ct1, wj ? 0 : ct1, wj ? HH : (j + 1)};

        const float* ib = ins + bl * CHB;

        f2_t acc[8][4];
#pragma unroll
        for (int k = 0; k < 8; k++) {
            f2_t bv = pk2(bs[child * 16 + 2 * k], bs[child * 16 + 2 * k + 1]);
            acc[k][0] = bv; acc[k][1] = bv; acc[k][2] = bv; acc[k][3] = bv;
        }

#pragma unroll 4
        for (int ci = 0; ci < 16; ci++) {
            const float* cb = ib + ci * CB;
            float xv[4][4];
#pragma unroll
            for (int a = 0; a < 4; a++)
#pragma unroll
                for (int b = 0; b < 4; b++)
                    xv[a][b] = cb[rt[a] + ct[b]];

#pragma unroll
            for (int kh = 0; kh < 2; kh++)
#pragma unroll
                for (int kw = 0; kw < 2; kw++) {
                    const ulonglong2* wt2 =
                        (const ulonglong2*)(wc + (ci * 4 + kh * 2 + kw) * 16);
                    f2_t vs0 = pk2(xv[kh][kw],         xv[kh][kw]);
                    f2_t vs1 = pk2(xv[kh][2 + kw],     xv[kh][2 + kw]);
                    f2_t vs2 = pk2(xv[2 + kh][kw],     xv[2 + kh][kw]);
                    f2_t vs3 = pk2(xv[2 + kh][2 + kw], xv[2 + kh][2 + kw]);
#pragma unroll
                    for (int m = 0; m < 4; m++) {
                        ulonglong2 ww = wt2[m];
                        acc[2 * m][0]     = fma2(ww.x, vs0, acc[2 * m][0]);
                        acc[2 * m][1]     = fma2(ww.x, vs1, acc[2 * m][1]);
                        acc[2 * m][2]     = fma2(ww.x, vs2, acc[2 * m][2]);
                        acc[2 * m][3]     = fma2(ww.x, vs3, acc[2 * m][3]);
                        acc[2 * m + 1][0] = fma2(ww.y, vs0, acc[2 * m + 1][0]);
                        acc[2 * m + 1][1] = fma2(ww.y, vs1, acc[2 * m + 1][1]);
                        acc[2 * m + 1][2] = fma2(ww.y, vs2, acc[2 * m + 1][2]);
                        acc[2 * m + 1][3] = fma2(ww.y, vs3, acc[2 * m + 1][3]);
                    }
                }
        }

        float* ob = out + ((size_t)(b0 + bl) * Nout + nprime) * 16 * HH
                        + i * H + j;
#pragma unroll
        for (int k = 0; k < 8; k++) {
            float a0, c0, a1, c1, a2, c2, a3, c3;
            upk2(acc[k][0], a0, c0);
            upk2(acc[k][1], a1, c1);
            upk2(acc[k][2], a2, c2);
            upk2(acc[k][3], a3, c3);
            float e = fmaxf(a0, 0.f) + fmaxf(a1, 0.f) + fmaxf(a2, 0.f) + fmaxf(a3, 0.f);
            float o = fmaxf(c0, 0.f) + fmaxf(c1, 0.f) + fmaxf(c2, 0.f) + fmaxf(c3, 0.f);
            ob[(2 * k) * HH]     = 0.25f * e;
            ob[(2 * k + 1) * HH] = 0.25f * o;
        }
    }
}

// ---------------------------------------------------------------------------
// Layer 4 special (S=4): conv grid is 3x3 = 9 distinct cells but the pool-tap
// formulation computes 16 -> 1.78x waste. Compute each cell ONCE (acc = 9
// cells x 4 oc-pairs), then pool with relu+avg in the epilogue using the wrap
// mapping (i=1 row taps -> cells {2,0}; same for cols). Splat-once-per-input
// ordering: per ci, 16 LDS + 8 LDS.128 + 16 pk2 + 144 fma2.
// Thread = (child=warp&3, half=warp>>2, bl=lane+32*it). CHB=257 (conflict-free).
// ---------------------------------------------------------------------------
__global__ __launch_bounds__(256, 2)
void k_layer4(const float* __restrict__ in, const float* __restrict__ W,
              const float* __restrict__ bias, float* __restrict__ out)
{
    constexpr int G = 16, Nin = 256, Nout = 1024, BB = 64;
    constexpr int CHB = 257;    // 16*16 + 1  (≡ 1 mod 32)
    constexpr int WCS = 1024;

    extern __shared__ float sm[];
    float* ws  = sm;            // 4*WCS
    float* bs  = sm + 4 * WCS;  // 64
    float* ins = bs + 64;       // BB*CHB

    const int tid = threadIdx.x;
    const int n = blockIdx.x;
    const int b0 = blockIdx.y * BB;

    const float* Wg = W + (size_t)n * 4096;
    for (int t = tid; t < 4096; t += 256) {
        int ol = t >> 6, tap = t & 63;
        ws[(ol >> 4) * WCS + tap * 16 + (ol & 15)] = Wg[t];
    }
    if (tid < 64) bs[tid] = bias[n * 64 + tid];

    // inputs row-major per ci: rem = ci*16 + r*4 + c (matches gmem layout)
    for (int t = tid; t < BB * 256; t += 256) {
        int bl = t >> 8, rem = t & 255;
        ins[bl * CHB + rem] = in[((size_t)(b0 + bl) * Nin + n) * 256 + rem];
    }
    __syncthreads();

    const int Ay = n / G, Ax = n % G;
    const int lane = tid & 31, warp = tid >> 5;
    const int child = warp & 3;
    const int half = warp >> 2;       // 0/1
    const float* wc = ws + child * WCS + half * 8;
    const int yl = child >> 1, xl = child & 1;
    const int nprime = (2 * Ay + yl) * (2 * G) + (2 * Ax + xl);

#pragma unroll
    for (int it = 0; it < 2; it++) {
        const int bl = lane + (it << 5);
        const float* ib = ins + bl * CHB;

        f2_t acc[9][4];   // [cell r*3+c][oc-pair]
#pragma unroll
        for (int m = 0; m < 4; m++) {
            f2_t bv = pk2(bs[child * 16 + half * 8 + 2 * m],
                          bs[child * 16 + half * 8 + 2 * m + 1]);
#pragma unroll
            for (int cell = 0; cell < 9; cell++) acc[cell][m] = bv;
        }

#pragma unroll 2
        for (int ci = 0; ci < 16; ci++) {
            // hoist this ci's 4 tap-weight vectors (8 oc = 4 f2 each)
            f2_t w[4][4];
#pragma unroll
            for (int tap = 0; tap < 4; tap++) {
                const ulonglong2* wt2 =
                    (const ulonglong2*)(wc + (ci * 4 + tap) * 16);
                ulonglong2 u0 = wt2[0];
                ulonglong2 u1 = wt2[1];
                w[tap][0] = u0.x; w[tap][1] = u0.y;
                w[tap][2] = u1.x; w[tap][3] = u1.y;
            }
            // loop input cells; each contributes to all valid conv cells
#pragma unroll
            for (int a = 0; a < 4; a++)
#pragma unroll
                for (int b = 0; b < 4; b++) {
                    float x = ib[ci * 16 + a * 4 + b];
                    f2_t vs = pk2(x, x);
#pragma unroll
                    for (int kh = 0; kh < 2; kh++) {
                        if (a - kh < 0 || a - kh > 2) continue;
#pragma unroll
                        for (int kw = 0; kw < 2; kw++) {
                            if (b - kw < 0 || b - kw > 2) continue;
                            const int tap = kh * 2 + kw;
                            const int cell = (a - kh) * 3 + (b - kw);
#pragma unroll
                            for (int m = 0; m < 4; m++)
                                acc[cell][m] = fma2(w[tap][m], vs, acc[cell][m]);
                        }
                    }
                }
        }

        // epilogue: relu cells, pool 2x2 with wrap (row/col taps: 0->{0,1},
        // 1->{2,0}), write float4 per channel.
        float* ob = out + ((size_t)(b0 + bl) * Nout + nprime) * 64
                        + half * 32;
#pragma unroll
        for (int m = 0; m < 4; m++) {
            float ce[9], co[9];
#pragma unroll
            for (int cell = 0; cell < 9; cell++) {
                float a0, a1;
                upk2(acc[cell][m], a0, a1);
                ce[cell] = fmaxf(a0, 0.f);
                co[cell] = fmaxf(a1, 0.f);
            }
            float4 oe, oo;
            // pooled (i,j): rows {2i, wrap}, cols {2j, wrap}
            // i=0 rows {0,1}; i=1 rows {2,0}; same for cols.
            oe.x = ce[0*3+0] + ce[0*3+1] + ce[1*3+0] + ce[1*3+1]; // (0,0)
            oe.y = ce[0*3+2] + ce[0*3+0] + ce[1*3+2] + ce[1*3+0]; // (0,1)
            oe.z = ce[2*3+0] + ce[2*3+1] + ce[0*3+0] + ce[0*3+1]; // (1,0)
            oe.w = ce[2*3+2] + ce[2*3+0] + ce[0*3+2] + ce[0*3+0]; // (1,1)
            oo.x = co[0*3+0] + co[0*3+1] + co[1*3+0] + co[1*3+1];
            oo.y = co[0*3+2] + co[0*3+0] + co[1*3+2] + co[1*3+0];
            oo.z = co[2*3+0] + co[2*3+1] + co[0*3+0] + co[0*3+1];
            oo.w = co[2*3+2] + co[2*3+0] + co[0*3+2] + co[0*3+0];
            oe.x *= 0.25f; oe.y *= 0.25f; oe.z *= 0.25f; oe.w *= 0.25f;
            oo.x *= 0.25f; oo.y *= 0.25f; oo.z *= 0.25f; oo.w *= 0.25f;
            *(float4*)(ob + (2 * m) * 4)     = oe;
            *(float4*)(ob + (2 * m + 1) * 4) = oo;
        }
    }
}

// ---------------------------------------------------------------------------
// Layer 5 special (R15-proven): out = relu(bias + conv), 4 batch slots/thread.
// ---------------------------------------------------------------------------
__global__ __launch_bounds__(256, 2)
void k_layer5(const float* __restrict__ in, const float* __restrict__ W,
              const float* __restrict__ bias, float* __restrict__ out)
{
    constexpr int G = 32, Nin = 1024, Nout = 4096, BB = 256;
    constexpr int CHB = 65;
    constexpr int WCS = 1024;

    extern __shared__ float sm[];
    float* ws  = sm;
    float* bs  = sm + 4 * WCS;
    float* ins = bs + 64;

    const int tid = threadIdx.x;
    const int n = blockIdx.x;

    const float* Wg = W + (size_t)n * 4096;
    for (int t = tid; t < 4096; t += 256) {
        int ol = t >> 6, tap = t & 63;
        ws[(ol >> 4) * WCS + tap * 16 + (ol & 15)] = Wg[t];
    }
    if (tid < 64) bs[tid] = bias[n * 64 + tid];

    for (int t = tid; t < BB * 64; t += 256) {
        int bl = t >> 6, rem = t & 63;
        ins[bl * CHB + rem] = in[((size_t)bl * Nin + n) * 64 + rem];
    }
    __syncthreads();

    const int Ay = n / G, Ax = n % G;
    const int lane = tid & 31, warp = tid >> 5;
    const int child = warp & 3;
    const int wk0 = lane + ((warp >> 2) << 5);

    const float* wc = ws + child * WCS;
    const int yl = child >> 1, xl = child & 1;
    const int nprime = (2 * Ay + yl) * (2 * G) + (2 * Ax + xl);

    const float* ib = ins + wk0 * CHB;

    f2_t acc[8][4];
#pragma unroll
    for (int k = 0; k < 8; k++) {
        f2_t bv = pk2(bs[child * 16 + 2 * k], bs[child * 16 + 2 * k + 1]);
        acc[k][0] = bv; acc[k][1] = bv; acc[k][2] = bv; acc[k][3] = bv;
    }

#pragma unroll 4
    for (int ci = 0; ci < 16; ci++) {
#pragma unroll
        for (int t = 0; t < 4; t++) {
            float x0 = ib[ci * 4 + t];
            float x1 = ib[64 * CHB + ci * 4 + t];
            float x2 = ib[128 * CHB + ci * 4 + t];
            float x3 = ib[192 * CHB + ci * 4 + t];
            const ulonglong2* wt2 = (const ulonglong2*)(wc + (ci * 4 + t) * 16);
            f2_t vs0 = pk2(x0, x0), vs1 = pk2(x1, x1);
            f2_t vs2 = pk2(x2, x2), vs3 = pk2(x3, x3);
#pragma unroll
            for (int m = 0; m < 4; m++) {
                ulonglong2 ww = wt2[m];
                acc[2 * m][0]     = fma2(ww.x, vs0, acc[2 * m][0]);
                acc[2 * m][1]     = fma2(ww.x, vs1, acc[2 * m][1]);
                acc[2 * m][2]     = fma2(ww.x, vs2, acc[2 * m][2]);
                acc[2 * m][3]     = fma2(ww.x, vs3, acc[2 * m][3]);
                acc[2 * m + 1][0] = fma2(ww.y, vs0, acc[2 * m + 1][0]);
                acc[2 * m + 1][1] = fma2(ww.y, vs1, acc[2 * m + 1][1]);
                acc[2 * m + 1][2] = fma2(ww.y, vs2, acc[2 * m + 1][2]);
                acc[2 * m + 1][3] = fma2(ww.y, vs3, acc[2 * m + 1][3]);
            }
        }
    }

#pragma unroll
    for (int s = 0; s < 4; s++) {
        const int bl = wk0 + 64 * s;
        float* ob = out + ((size_t)bl * Nout + nprime) * 16;
#pragma unroll
        for (int q = 0; q < 4; q++) {
            float a0, a1, a2, a3;
            upk2(acc[2 * q][s], a0, a1);
            upk2(acc[2 * q + 1][s], a2, a3);
            float4 o;
            o.x = fmaxf(a0, 0.f); o.y = fmaxf(a1, 0.f);
            o.z = fmaxf(a2, 0.f); o.w = fmaxf(a3, 0.f);
            *(float4*)(ob + 4 * q) = o;
        }
    }
}

// ---------------------------------------------------------------------------
// FT layer with smem-cached Wft (R14-proven).
// ---------------------------------------------------------------------------
__global__ __launch_bounds__(256)
void k_ft(const float* __restrict__ v, const float* __restrict__ Wft,
          const float* __restrict__ bft, float* __restrict__ out)
{
    constexpr int WROW = 65;
    extern __shared__ float sm[];
    float* ws = sm;
    float* bs = sm + 256 * WROW;

    const int tid = threadIdx.x;
    const int nb = blockIdx.x;
    const int yb = blockIdx.y;

    for (int t = tid; t < 256 * 64; t += 256) {
        int r = t >> 6, c = t & 63;
        ws[r * WROW + c] = Wft[(size_t)nb * 16384 + t];
    }
    for (int t = tid; t < 1024; t += 256)
        bs[t] = bft[nb * 1024 + t];
    __syncthreads();

    const int n = nb * 256 + tid;
    const float* wp = ws + tid * WROW;

#pragma unroll 1
    for (int bb = 0; bb < 16; bb++) {
        const int b = yb * 16 + bb;
        const float* vp = v + ((size_t)b * 4096 + n) * 16;
        float vv[16];
#pragma unroll
        for (int c = 0; c < 16; c += 4) {
            float4 t = *(const float4*)(vp + c);
            vv[c] = t.x; vv[c + 1] = t.y; vv[c + 2] = t.z; vv[c + 3] = t.w;
        }
        float f[4];
#pragma unroll
        for (int o = 0; o < 4; o++) {
            float acc = bs[tid * 4 + o];
#pragma unroll
            for (int c = 0; c < 16; c++) acc = fmaf(vv[c], wp[o * 16 + c], acc);
            f[o] = acc;
        }
        out[(size_t)b * 8192 + n]        = f[0] - f[1];
        out[(size_t)b * 8192 + 4096 + n] = f[2] - f[3];
    }
}

// ---------------------------------------------------------------------------

template <int S, int BB>
static inline int smem_b() {
    int HH = (S / 2) * (S / 2);
    int pad = (HH < 32) ? HH : 0;
    return (4 * 1024 + 64 + BB * (16 * S * S + pad)) * 4;
}

extern "C" void kernel_launch(void* const* d_in, const int* in_sizes, int n_in,
                              void* d_out, int out_size)
{
    (void)n_in; (void)out_size;
    const float* x  = (const float*)d_in[0];
    const float* W0 = (const float*)d_in[1];
    const float* b0 = (const float*)d_in[2];
    const float *W1, *b1, *W2, *b2, *W3, *b3, *W4, *b4, *W5, *b5, *Wft, *bft;
    if (in_sizes[3] == 262144) {
        Wft = (const float*)d_in[3];  bft = (const float*)d_in[4];
        W1 = (const float*)d_in[5];   b1 = (const float*)d_in[6];
        W2 = (const float*)d_in[7];   b2 = (const float*)d_in[8];
        W3 = (const float*)d_in[9];   b3 = (const float*)d_in[10];
        W4 = (const float*)d_in[11];  b4 = (const float*)d_in[12];
        W5 = (const float*)d_in[13];  b5 = (const float*)d_in[14];
    } else {
        W1 = (const float*)d_in[3];   b1 = (const float*)d_in[4];
        W2 = (const float*)d_in[5];   b2 = (const float*)d_in[6];
        W3 = (const float*)d_in[7];   b3 = (const float*)d_in[8];
        W4 = (const float*)d_in[9];   b4 = (const float*)d_in[10];
        W5 = (const float*)d_in[11];  b5 = (const float*)d_in[12];
        Wft = (const float*)d_in[13]; bft = (const float*)d_in[14];
    }
    float* out = (float*)d_out;

    float *bufA, *bufB;
    cudaGetSymbolAddress((void**)&bufA, g_bufA);
    cudaGetSymbolAddress((void**)&bufB, g_bufB);

    const int s1 = smem_b<32, 1>();                  // ~82 KB
    const int s2 = smem_b<16, 4>();                  // ~82 KB
    const int s3 = smem_b<8, 16>();                  // ~83 KB
    const int s4 = (4 * 1024 + 64 + 64 * 257) * 4;   // ~82 KB
    const int s5 = (4 * 1024 + 64 + 256 * 65) * 4;   // ~83 KB
    const int sft = (256 * 65 + 1024) * 4;           // ~70 KB
    cudaFuncSetAttribute(k_layer<32, 1, 2>,    cudaFuncAttributeMaxDynamicSharedMemorySize, s1);
    cudaFuncSetAttribute(k_layer<16, 4, 4>,    cudaFuncAttributeMaxDynamicSharedMemorySize, s2);
    cudaFuncSetAttribute(k_layer<8, 16, 8>,    cudaFuncAttributeMaxDynamicSharedMemorySize, s3);
    cudaFuncSetAttribute(k_layer4,             cudaFuncAttributeMaxDynamicSharedMemorySize, s4);
    cudaFuncSetAttribute(k_layer5,             cudaFuncAttributeMaxDynamicSharedMemorySize, s5);
    cudaFuncSetAttribute(k_ft,                 cudaFuncAttributeMaxDynamicSharedMemorySize, sft);

    k_layer0<<<dim3(4, BATCH), 256>>>(x, W0, b0, bufA);
    k_layer<32, 1, 2><<<dim3(4, 256), 256, s1>>>(bufA, W1, b1, bufB);
    k_layer<16, 4, 4><<<dim3(16, 64), 256, s2>>>(bufB, W2, b2, bufA);
    k_layer<8, 16, 8><<<dim3(64, 16), 256, s3>>>(bufA, W3, b3, bufB);
    k_layer4<<<dim3(256, 4), 256, s4>>>(bufB, W4, b4, bufA);
    k_layer5<<<dim3(1024, 1), 256, s5>>>(bufA, W5, b5, bufB);
    k_ft<<<dim3(16, 16), 256, sft>>>(bufB, Wft, bft, out);
}